// round 6
// baseline (speedup 1.0000x reference)
#include <cuda_runtime.h>
#include <cstdint>

#define BATCH 512
#define TSEQ  64
#define P_DIM 8
#define Q_DIM 24
#define N_DIM 32
#define PQ    (P_DIM * Q_DIM)   // 192
#define CPAD  36                // padded column stride (words) for 32-row panels
#define RPAD  12                // padded row stride for row-major 32x8 panels

// ---------------------------------------------------------------------------
// Single fused kernel. Block b handles question-seq b AND answer-seq b.
//
// Panel recurrence (quadratic Cayley, error 2||X||^3 ~ 1e-6/step):
//   G  = X C
//   C' = C - 2G + 2XG
// with X = [[0, x],[-x^T, 0]], x = 8x24, C = 32x8 panel.
//
// Thread layout (256 threads):
//   tid < 128 : question panel (p=0, warps 0-3); else answer (p=1, warps 4-7)
//   tp = tid & 127
//   tp <  64 : "top"    — owns entry (r=tp>>3, c=tp&7); 24 FMA/phase
//   tp >= 64 : "bottom" — owns rows 8+3*jg+{0,1,2}, col c (jg=(tp-64)>>3, c=tp&7)
// Own C/G entries live in registers; shared holds only cross-read copies.
// Panels synchronize independently via named barriers (ids 1 and 2).
// ---------------------------------------------------------------------------
__global__ __launch_bounds__(256, 4) void fused_kernel(
    const int*   __restrict__ s1,
    const int*   __restrict__ s2,
    const float* __restrict__ emb_q,
    const float* __restrict__ emb_a,
    const float* __restrict__ transforms,
    const float* __restrict__ bias,
    const float* __restrict__ wf,
    const float* __restrict__ wb,
    float*       __restrict__ out)
{
    const int b   = blockIdx.x;
    const int tid = threadIdx.x;
    const bool is_q = (tid < 128);
    const int  p    = is_q ? 0 : 1;
    const int  tp   = tid & 127;
    const bool top  = (tp < 64);
    const int  barid = p + 1;

    __shared__ __align__(16) float sx [2][2][PQ];    // [panel][buf] row-major 8x24
    __shared__ __align__(16) float sxT[2][2][PQ];    // [panel][buf] transposed 24x8
    __shared__ __align__(16) float sC[2][8 * CPAD];  // column-major padded
    __shared__ __align__(16) float sG[2][8 * CPAD];
    __shared__ int   stok[2][TSEQ];
    // epilogue scratch
    __shared__ __align__(16) float syb[N_DIM * CPAD];
    __shared__ __align__(16) float sUq[N_DIM * RPAD];
    __shared__ __align__(16) float sCa[N_DIM * RPAD];
    __shared__ float sA8[8 * 16];
    __shared__ float sW8[PQ];
    __shared__ float sbias[PQ];
    __shared__ float red[8];

    const float* emb  = is_q ? emb_q : emb_a;
    const int*   sent = is_q ? s1    : s2;

    // transforms cached in regs (answer panel: identity)
    float tf1 = 1.0f, tf2 = 1.0f;
    if (is_q) {
        tf1 = transforms[tp];
        if (top) tf2 = transforms[tp + 128];
    }

    if (top) stok[p][tp] = sent[b * TSEQ + tp];

    float* sCp = sC[p];
    float* sGp = sG[p];

    // geometry
    const int c  = tp & 7;
    const int r  = tp >> 3;              // top only
    const int jg = (tp - 64) >> 3;       // bottom only
    const int j0 = 3 * jg;
    // transpose-commit indices for the x loader
    const int i1 = tp / 24,        jj1 = tp % 24;
    const int i2 = (tp + 128) / 24, jj2 = (tp + 128) % 24;

    // registers: own panel entries
    float cown0 = 0.f, cown1 = 0.f, cown2 = 0.f;   // top uses cown0 only
    if (top) cown0 = (r == c) ? 1.0f : 0.0f;

    // init shared C
    if (top) {
        sCp[c * CPAD + r] = cown0;
    } else {
        sCp[c * CPAD + 8 + j0 + 0] = 0.0f;
        sCp[c * CPAD + 8 + j0 + 1] = 0.0f;
        sCp[c * CPAD + 8 + j0 + 2] = 0.0f;
    }
    __syncthreads();

    // first x (t = 63) into buffer 1 (both layouts)
    {
        int tok = stok[p][TSEQ - 1];
        float v1 = emb[(size_t)tok * PQ + tp] * tf1;
        sx [p][1][tp] = v1;
        sxT[p][1][jj1 * 8 + i1] = v1;
        if (top) {
            float v2 = emb[(size_t)tok * PQ + tp + 128] * tf2;
            sx [p][1][tp + 128] = v2;
            sxT[p][1][jj2 * 8 + i2] = v2;
        }
    }
    __syncthreads();

    float rx[24];

    #pragma unroll 2
    for (int t = TSEQ - 1; t >= 0; --t) {
        const int buf = t & 1;

        // prefetch next token's embedding row (L2-resident after warmup)
        float xn1 = 0.0f, xn2 = 0.0f;
        if (t > 0) {
            int tok = stok[p][t - 1];
            xn1 = emb[(size_t)tok * PQ + tp];
            if (top) xn2 = emb[(size_t)tok * PQ + tp + 128];
        }

        // cache this step's x slice in registers
        if (top) {
            const float4* px = (const float4*)(sx[p][buf] + r * Q_DIM);
            #pragma unroll
            for (int m = 0; m < 6; ++m) {
                float4 v = px[m];
                rx[4*m] = v.x; rx[4*m+1] = v.y; rx[4*m+2] = v.z; rx[4*m+3] = v.w;
            }
        } else {
            #pragma unroll
            for (int d = 0; d < 3; ++d) {
                const float4* pxt = (const float4*)(sxT[p][buf] + (j0 + d) * 8);
                float4 v0 = pxt[0], v1 = pxt[1];
                rx[d*8+0] = v0.x; rx[d*8+1] = v0.y; rx[d*8+2] = v0.z; rx[d*8+3] = v0.w;
                rx[d*8+4] = v1.x; rx[d*8+5] = v1.y; rx[d*8+6] = v1.z; rx[d*8+7] = v1.w;
            }
        }

        // ---- Phase 1: G = X C (cross reads of C only)
        float gown0, gown1 = 0.f, gown2 = 0.f;
        if (top) {
            const float4* pc = (const float4*)(&sCp[c * CPAD + 8]);
            float a0 = 0.f, a1 = 0.f, a2 = 0.f, a3 = 0.f;
            #pragma unroll
            for (int m = 0; m < 6; ++m) {
                float4 v = pc[m];
                a0 += rx[4*m] * v.x;  a1 += rx[4*m+1] * v.y;
                a2 += rx[4*m+2] * v.z; a3 += rx[4*m+3] * v.w;
            }
            gown0 = (a0 + a1) + (a2 + a3);
            sGp[c * CPAD + r] = gown0;
        } else {
            const float4* pc = (const float4*)(&sCp[c * CPAD]);
            float4 v0 = pc[0], v1 = pc[1];
            #pragma unroll
            for (int d = 0; d < 3; ++d) {
                float g = rx[d*8+0]*v0.x + rx[d*8+1]*v0.y + rx[d*8+2]*v0.z + rx[d*8+3]*v0.w
                        + rx[d*8+4]*v1.x + rx[d*8+5]*v1.y + rx[d*8+6]*v1.z + rx[d*8+7]*v1.w;
                g = -g;
                if (d == 0) gown0 = g; else if (d == 1) gown1 = g; else gown2 = g;
                sGp[c * CPAD + 8 + j0 + d] = g;
            }
        }
        asm volatile("bar.sync %0, %1;" :: "r"(barid), "r"(128) : "memory");

        // ---- Phase 2: C' = C - 2G + 2XG (cross reads of G only; C' in place)
        if (top) {
            const float4* pg = (const float4*)(&sGp[c * CPAD + 8]);
            float a0 = 0.f, a1 = 0.f, a2 = 0.f, a3 = 0.f;
            #pragma unroll
            for (int m = 0; m < 6; ++m) {
                float4 v = pg[m];
                a0 += rx[4*m] * v.x;  a1 += rx[4*m+1] * v.y;
                a2 += rx[4*m+2] * v.z; a3 += rx[4*m+3] * v.w;
            }
            float h = (a0 + a1) + (a2 + a3);
            cown0 += 2.0f * (h - gown0);
            sCp[c * CPAD + r] = cown0;
        } else {
            const float4* pg = (const float4*)(&sGp[c * CPAD]);
            float4 v0 = pg[0], v1 = pg[1];
            #pragma unroll
            for (int d = 0; d < 3; ++d) {
                float h = rx[d*8+0]*v0.x + rx[d*8+1]*v0.y + rx[d*8+2]*v0.z + rx[d*8+3]*v0.w
                        + rx[d*8+4]*v1.x + rx[d*8+5]*v1.y + rx[d*8+6]*v1.z + rx[d*8+7]*v1.w;
                h = -h;
                float go = (d == 0) ? gown0 : ((d == 1) ? gown1 : gown2);
                float cn = ((d == 0) ? cown0 : ((d == 1) ? cown1 : cown2)) + 2.0f * (h - go);
                if (d == 0) cown0 = cn; else if (d == 1) cown1 = cn; else cown2 = cn;
                sCp[c * CPAD + 8 + j0 + d] = cn;
            }
        }

        // commit next x into the other buffer (readers consume after the barrier)
        if (t > 0) {
            const int nb = buf ^ 1;
            float v1 = xn1 * tf1;
            sx [p][nb][tp] = v1;
            sxT[p][nb][jj1 * 8 + i1] = v1;
            if (top) {
                float v2 = xn2 * tf2;
                sx [p][nb][tp + 128] = v2;
                sxT[p][nb][jj2 * 8 + i2] = v2;
            }
        }
        asm volatile("bar.sync %0, %1;" :: "r"(barid), "r"(128) : "memory");
    }

    __syncthreads();

    // =====================  EPILOGUE  =====================
    // 1) yb = cayley(tangent(bias)) via exact 8x8 Gauss-Jordan (redundant per block)
    if (tid < PQ) sbias[tid] = bias[tid];
    __syncthreads();

    if (tid < 128) {
        int i = tid >> 4, cc = tid & 15;
        float v;
        if (cc < 8) {
            v = (i == cc) ? 1.0f : 0.0f;
            #pragma unroll
            for (int k = 0; k < Q_DIM; ++k) v += sbias[i * Q_DIM + k] * sbias[cc * Q_DIM + k];
        } else {
            v = (i == cc - 8) ? 1.0f : 0.0f;
        }
        sA8[i * 16 + cc] = v;
    }
    __syncthreads();

    for (int k = 0; k < 8; ++k) {
        float nv = 0.0f;
        int i = tid >> 4, cc = tid & 15;
        if (tid < 128) {
            float piv = 1.0f / sA8[k * 16 + k];
            float akc = sA8[k * 16 + cc] * piv;
            nv = (i == k) ? akc : (sA8[i * 16 + cc] - sA8[i * 16 + k] * akc);
        }
        __syncthreads();
        if (tid < 128) sA8[i * 16 + cc] = nv;
        __syncthreads();
    }

    if (tid < PQ) {
        int i = tid / Q_DIM, jj = tid % Q_DIM;
        float w = 0.0f;
        #pragma unroll
        for (int k = 0; k < 8; ++k) w += sA8[i * 16 + 8 + k] * sbias[k * Q_DIM + jj];
        sW8[tid] = w;
    }
    __syncthreads();

    #pragma unroll
    for (int e = 0; e < 4; ++e) {
        int idx = tid + 256 * e;
        int rr = idx >> 5, cc = idx & 31;
        float y;
        if (rr < 8 && cc < 8) {
            y = 2.0f * sA8[rr * 16 + 8 + cc] - ((rr == cc) ? 1.0f : 0.0f);
        } else if (rr < 8) {
            y = -2.0f * sW8[rr * Q_DIM + (cc - 8)];
        } else if (cc < 8) {
            y = 2.0f * sW8[cc * Q_DIM + (rr - 8)];
        } else {
            int jj = rr - 8, c2 = cc - 8;
            float acc = 0.0f;
            #pragma unroll
            for (int i = 0; i < 8; ++i) acc += sbias[i * Q_DIM + jj] * sW8[i * Q_DIM + c2];
            y = ((jj == c2) ? 1.0f : 0.0f) - 2.0f * acc;
        }
        syb[rr * CPAD + cc] = y;
    }
    __syncthreads();

    // 2) U_q = yb * C_q (row-major), C_a transposed to row-major
    {
        int rr = tid >> 3, cc = tid & 7;
        const float4* yr = (const float4*)(&syb[rr * CPAD]);
        const float4* cq = (const float4*)(&sC[0][cc * CPAD]);
        float a0 = 0.f, a1 = 0.f, a2 = 0.f, a3 = 0.f;
        #pragma unroll
        for (int m = 0; m < 8; ++m) {
            float4 yv = yr[m];
            float4 cv = cq[m];
            a0 += yv.x * cv.x; a1 += yv.y * cv.y; a2 += yv.z * cv.z; a3 += yv.w * cv.w;
        }
        sUq[rr * RPAD + cc] = (a0 + a1) + (a2 + a3);
        sCa[rr * RPAD + cc] = sC[1][cc * CPAD + rr];
    }
    __syncthreads();

    // 3) dist^2 = || Uq Uq^T - Ca Ca^T ||_F^2
    float acc = 0.0f;
    #pragma unroll
    for (int e = 0; e < 4; ++e) {
        int idx = tid + 256 * e;
        int i = idx >> 5, jj = idx & 31;
        const float4* ui = (const float4*)(&sUq[i  * RPAD]);
        const float4* uj = (const float4*)(&sUq[jj * RPAD]);
        const float4* ai = (const float4*)(&sCa[i  * RPAD]);
        const float4* aj = (const float4*)(&sCa[jj * RPAD]);
        float d = 0.0f;
        #pragma unroll
        for (int m = 0; m < 2; ++m) {
            float4 a = ui[m], bq = uj[m], x = ai[m], y = aj[m];
            d += a.x * bq.x + a.y * bq.y + a.z * bq.z + a.w * bq.w;
            d -= x.x * y.x  + x.y * y.y  + x.z * y.z  + x.w * y.w;
        }
        acc += d * d;
    }

    #pragma unroll
    for (int off = 16; off > 0; off >>= 1)
        acc += __shfl_xor_sync(0xFFFFFFFFu, acc, off);
    if ((tid & 31) == 0) red[tid >> 5] = acc;
    __syncthreads();
    if (tid == 0) {
        float s = 0.0f;
        #pragma unroll
        for (int w = 0; w < 8; ++w) s += red[w];
        out[b] = -(*wf) * sqrtf(s) + (*wb);
    }
}

// ---------------------------------------------------------------------------
extern "C" void kernel_launch(void* const* d_in, const int* in_sizes, int n_in,
                              void* d_out, int out_size)
{
    const int*   s1 = (const int*)  d_in[0];   // sentence_1 [512,64]
    const int*   s2 = (const int*)  d_in[1];   // sentence_2 [512,64]
    const float* qe = (const float*)d_in[2];   // question_embedding [32000,8,24]
    const float* ae = (const float*)d_in[3];   // answer_embedding   [32000,8,24]
    const float* qt = (const float*)d_in[4];   // question_transforms [8,24]
    const float* qb = (const float*)d_in[5];   // question_bias [8,24]
    const float* wf = (const float*)d_in[6];
    const float* wb = (const float*)d_in[7];
    float* out = (float*)d_out;

    fused_kernel<<<BATCH, 256>>>(s1, s2, qe, ae, qt, qb, wf, wb, out);
}

// round 7
// speedup vs baseline: 1.0696x; 1.0696x over previous
#include <cuda_runtime.h>
#include <cstdint>

#define BATCH 512
#define TSEQ  64
#define P_DIM 8
#define Q_DIM 24
#define N_DIM 32
#define PQ    (P_DIM * Q_DIM)   // 192
#define CPAD  36                // padded column stride (words) for 32-row panels
#define RPAD  12                // padded row stride for row-major 32x8 panels

// ---------------------------------------------------------------------------
// Single fused kernel. Block b handles question-seq b AND answer-seq b.
//
// Panel recurrence (quadratic Cayley, error 2||X||^3 ~ 1e-6/step):
//   G  = X C
//   C' = C - 2G + 2XG
// with X = [[0, x],[-x^T, 0]], x = 8x24, C = 32x8 panel (column-major, CPAD).
//
// Thread layout (256 threads):
//   tid < 128 : question panel (p=0); else answer panel (p=1)
//   tp = tid & 127
//   tp <  64 : "top"    — owns entry (r=tp>>3, c=tp&7); 24 FMA/phase
//   tp >= 64 : "bottom" — owns rows 8+3*jg+{0,1,2}, col c (jg=(tp-64)>>3, c=tp&7)
// Own C/G entries live in registers; shared holds only cross-read copies.
// ---------------------------------------------------------------------------
__global__ __launch_bounds__(256, 4) void fused_kernel(
    const int*   __restrict__ s1,
    const int*   __restrict__ s2,
    const float* __restrict__ emb_q,
    const float* __restrict__ emb_a,
    const float* __restrict__ transforms,
    const float* __restrict__ bias,
    const float* __restrict__ wf,
    const float* __restrict__ wb,
    float*       __restrict__ out)
{
    const int b   = blockIdx.x;
    const int tid = threadIdx.x;
    const bool is_q = (tid < 128);
    const int  p    = is_q ? 0 : 1;
    const int  tp   = tid & 127;
    const bool top  = (tp < 64);

    __shared__ __align__(16) float sx[2][2][PQ];     // [panel][buf] row-major 8x24
    __shared__ __align__(16) float sC[2][8 * CPAD];  // column-major padded
    __shared__ __align__(16) float sG[2][8 * CPAD];
    __shared__ int   stok[2][TSEQ];
    // epilogue scratch
    __shared__ __align__(16) float syb[N_DIM * CPAD];
    __shared__ __align__(16) float sUq[N_DIM * RPAD];
    __shared__ __align__(16) float sCa[N_DIM * RPAD];
    __shared__ float sA8[8 * 16];
    __shared__ float sW8[PQ];
    __shared__ float sbias[PQ];
    __shared__ float red[8];

    const float* emb  = is_q ? emb_q : emb_a;
    const int*   sent = is_q ? s1    : s2;

    // transforms cached in regs (answer panel: identity)
    float tf1 = 1.0f, tf2 = 1.0f;
    if (is_q) {
        tf1 = transforms[tp];
        if (top) tf2 = transforms[tp + 128];
    }

    if (top) stok[p][tp] = sent[b * TSEQ + tp];

    float* sCp = sC[p];
    float* sGp = sG[p];

    // geometry
    const int c  = tp & 7;
    const int r  = tp >> 3;              // top only
    const int jg = (tp - 64) >> 3;       // bottom only
    const int j0 = 3 * jg;

    // registers: own panel entries (top uses cown0 only)
    float cown0 = 0.f, cown1 = 0.f, cown2 = 0.f;
    if (top) cown0 = (r == c) ? 1.0f : 0.0f;

    // init shared C
    if (top) {
        sCp[c * CPAD + r] = cown0;
    } else {
        sCp[c * CPAD + 8 + j0 + 0] = 0.0f;
        sCp[c * CPAD + 8 + j0 + 1] = 0.0f;
        sCp[c * CPAD + 8 + j0 + 2] = 0.0f;
    }
    __syncthreads();

    // first x (t = 63) into buffer 1
    {
        int tok = stok[p][TSEQ - 1];
        sx[p][1][tp] = emb[(size_t)tok * PQ + tp] * tf1;
        if (top) sx[p][1][tp + 128] = emb[(size_t)tok * PQ + tp + 128] * tf2;
    }
    __syncthreads();

    float rx[24];

    for (int t = TSEQ - 1; t >= 0; --t) {
        const float* xb = sx[p][t & 1];

        // prefetch next token's embedding row (L2-resident after warmup)
        float xn1 = 0.0f, xn2 = 0.0f;
        if (t > 0) {
            int tok = stok[p][t - 1];
            xn1 = emb[(size_t)tok * PQ + tp];
            if (top) xn2 = emb[(size_t)tok * PQ + tp + 128];
        }

        // cache this step's x slice in registers
        if (top) {
            const float4* px = (const float4*)(xb + r * Q_DIM);
            #pragma unroll
            for (int m = 0; m < 6; ++m) {
                float4 v = px[m];
                rx[4*m] = v.x; rx[4*m+1] = v.y; rx[4*m+2] = v.z; rx[4*m+3] = v.w;
            }
        } else {
            #pragma unroll
            for (int i = 0; i < 8; ++i) {
                rx[i*3 + 0] = xb[i * Q_DIM + j0 + 0];
                rx[i*3 + 1] = xb[i * Q_DIM + j0 + 1];
                rx[i*3 + 2] = xb[i * Q_DIM + j0 + 2];
            }
        }

        // ---- Phase 1: G = X C (cross reads of C only)
        float gown0, gown1 = 0.f, gown2 = 0.f;
        if (top) {
            const float4* pc = (const float4*)(&sCp[c * CPAD + 8]);
            float a0 = 0.f, a1 = 0.f, a2 = 0.f, a3 = 0.f;
            #pragma unroll
            for (int m = 0; m < 6; ++m) {
                float4 v = pc[m];
                a0 += rx[4*m] * v.x;  a1 += rx[4*m+1] * v.y;
                a2 += rx[4*m+2] * v.z; a3 += rx[4*m+3] * v.w;
            }
            gown0 = (a0 + a1) + (a2 + a3);
            sGp[c * CPAD + r] = gown0;
        } else {
            const float4* pc = (const float4*)(&sCp[c * CPAD]);
            float4 v0 = pc[0], v1 = pc[1];
            #pragma unroll
            for (int d = 0; d < 3; ++d) {
                float g = rx[0*3+d]*v0.x + rx[1*3+d]*v0.y + rx[2*3+d]*v0.z + rx[3*3+d]*v0.w
                        + rx[4*3+d]*v1.x + rx[5*3+d]*v1.y + rx[6*3+d]*v1.z + rx[7*3+d]*v1.w;
                g = -g;
                if (d == 0) gown0 = g; else if (d == 1) gown1 = g; else gown2 = g;
                sGp[c * CPAD + 8 + j0 + d] = g;
            }
        }
        __syncthreads();

        // ---- Phase 2: C' = C - 2G + 2XG (cross reads of G only; in place)
        if (top) {
            const float4* pg = (const float4*)(&sGp[c * CPAD + 8]);
            float a0 = 0.f, a1 = 0.f, a2 = 0.f, a3 = 0.f;
            #pragma unroll
            for (int m = 0; m < 6; ++m) {
                float4 v = pg[m];
                a0 += rx[4*m] * v.x;  a1 += rx[4*m+1] * v.y;
                a2 += rx[4*m+2] * v.z; a3 += rx[4*m+3] * v.w;
            }
            float h = (a0 + a1) + (a2 + a3);
            cown0 += 2.0f * (h - gown0);
            sCp[c * CPAD + r] = cown0;
        } else {
            const float4* pg = (const float4*)(&sGp[c * CPAD]);
            float4 v0 = pg[0], v1 = pg[1];
            #pragma unroll
            for (int d = 0; d < 3; ++d) {
                float h = rx[0*3+d]*v0.x + rx[1*3+d]*v0.y + rx[2*3+d]*v0.z + rx[3*3+d]*v0.w
                        + rx[4*3+d]*v1.x + rx[5*3+d]*v1.y + rx[6*3+d]*v1.z + rx[7*3+d]*v1.w;
                h = -h;
                float go = (d == 0) ? gown0 : ((d == 1) ? gown1 : gown2);
                float cn = ((d == 0) ? cown0 : ((d == 1) ? cown1 : cown2)) + 2.0f * (h - go);
                if (d == 0) cown0 = cn; else if (d == 1) cown1 = cn; else cown2 = cn;
                sCp[c * CPAD + 8 + j0 + d] = cn;
            }
        }

        // commit next x into the other buffer (readers consume after the barrier)
        if (t > 0) {
            float* xo = sx[p][(t & 1) ^ 1];
            xo[tp] = xn1 * tf1;
            if (top) xo[tp + 128] = xn2 * tf2;
        }
        __syncthreads();
    }

    // =====================  EPILOGUE  =====================
    // 1) yb = cayley(tangent(bias)) via exact 8x8 Gauss-Jordan (redundant per block)
    if (tid < PQ) sbias[tid] = bias[tid];
    __syncthreads();

    if (tid < 128) {
        int i = tid >> 4, cc = tid & 15;
        float v;
        if (cc < 8) {
            v = (i == cc) ? 1.0f : 0.0f;
            #pragma unroll
            for (int k = 0; k < Q_DIM; ++k) v += sbias[i * Q_DIM + k] * sbias[cc * Q_DIM + k];
        } else {
            v = (i == cc - 8) ? 1.0f : 0.0f;
        }
        sA8[i * 16 + cc] = v;
    }
    __syncthreads();

    for (int k = 0; k < 8; ++k) {
        float nv = 0.0f;
        int i = tid >> 4, cc = tid & 15;
        if (tid < 128) {
            float piv = 1.0f / sA8[k * 16 + k];
            float akc = sA8[k * 16 + cc] * piv;
            nv = (i == k) ? akc : (sA8[i * 16 + cc] - sA8[i * 16 + k] * akc);
        }
        __syncthreads();
        if (tid < 128) sA8[i * 16 + cc] = nv;
        __syncthreads();
    }

    if (tid < PQ) {
        int i = tid / Q_DIM, jj = tid % Q_DIM;
        float w = 0.0f;
        #pragma unroll
        for (int k = 0; k < 8; ++k) w += sA8[i * 16 + 8 + k] * sbias[k * Q_DIM + jj];
        sW8[tid] = w;
    }
    __syncthreads();

    #pragma unroll
    for (int e = 0; e < 4; ++e) {
        int idx = tid + 256 * e;
        int rr = idx >> 5, cc = idx & 31;
        float y;
        if (rr < 8 && cc < 8) {
            y = 2.0f * sA8[rr * 16 + 8 + cc] - ((rr == cc) ? 1.0f : 0.0f);
        } else if (rr < 8) {
            y = -2.0f * sW8[rr * Q_DIM + (cc - 8)];
        } else if (cc < 8) {
            y = 2.0f * sW8[cc * Q_DIM + (rr - 8)];
        } else {
            int jj = rr - 8, c2 = cc - 8;
            float acc = 0.0f;
            #pragma unroll
            for (int i = 0; i < 8; ++i) acc += sbias[i * Q_DIM + jj] * sW8[i * Q_DIM + c2];
            y = ((jj == c2) ? 1.0f : 0.0f) - 2.0f * acc;
        }
        syb[rr * CPAD + cc] = y;
    }
    __syncthreads();

    // 2) U_q = yb * C_q (row-major), C_a transposed to row-major
    {
        int rr = tid >> 3, cc = tid & 7;
        const float4* yr = (const float4*)(&syb[rr * CPAD]);
        const float4* cq = (const float4*)(&sC[0][cc * CPAD]);
        float a0 = 0.f, a1 = 0.f, a2 = 0.f, a3 = 0.f;
        #pragma unroll
        for (int m = 0; m < 8; ++m) {
            float4 yv = yr[m];
            float4 cv = cq[m];
            a0 += yv.x * cv.x; a1 += yv.y * cv.y; a2 += yv.z * cv.z; a3 += yv.w * cv.w;
        }
        sUq[rr * RPAD + cc] = (a0 + a1) + (a2 + a3);
        sCa[rr * RPAD + cc] = sC[1][cc * CPAD + rr];
    }
    __syncthreads();

    // 3) dist^2 = || Uq Uq^T - Ca Ca^T ||_F^2
    float acc = 0.0f;
    #pragma unroll
    for (int e = 0; e < 4; ++e) {
        int idx = tid + 256 * e;
        int i = idx >> 5, jj = idx & 31;
        const float4* ui = (const float4*)(&sUq[i  * RPAD]);
        const float4* uj = (const float4*)(&sUq[jj * RPAD]);
        const float4* ai = (const float4*)(&sCa[i  * RPAD]);
        const float4* aj = (const float4*)(&sCa[jj * RPAD]);
        float d = 0.0f;
        #pragma unroll
        for (int m = 0; m < 2; ++m) {
            float4 a = ui[m], bq = uj[m], x = ai[m], y = aj[m];
            d += a.x * bq.x + a.y * bq.y + a.z * bq.z + a.w * bq.w;
            d -= x.x * y.x  + x.y * y.y  + x.z * y.z  + x.w * y.w;
        }
        acc += d * d;
    }

    #pragma unroll
    for (int off = 16; off > 0; off >>= 1)
        acc += __shfl_xor_sync(0xFFFFFFFFu, acc, off);
    if ((tid & 31) == 0) red[tid >> 5] = acc;
    __syncthreads();
    if (tid == 0) {
        float s = 0.0f;
        #pragma unroll
        for (int w = 0; w < 8; ++w) s += red[w];
        out[b] = -(*wf) * sqrtf(s) + (*wb);
    }
}

// ---------------------------------------------------------------------------
extern "C" void kernel_launch(void* const* d_in, const int* in_sizes, int n_in,
                              void* d_out, int out_size)
{
    const int*   s1 = (const int*)  d_in[0];   // sentence_1 [512,64]
    const int*   s2 = (const int*)  d_in[1];   // sentence_2 [512,64]
    const float* qe = (const float*)d_in[2];   // question_embedding [32000,8,24]
    const float* ae = (const float*)d_in[3];   // answer_embedding   [32000,8,24]
    const float* qt = (const float*)d_in[4];   // question_transforms [8,24]
    const float* qb = (const float*)d_in[5];   // question_bias [8,24]
    const float* wf = (const float*)d_in[6];
    const float* wb = (const float*)d_in[7];
    float* out = (float*)d_out;

    fused_kernel<<<BATCH, 256>>>(s1, s2, qe, ae, qt, qb, wf, wb, out);
}

// round 8
// speedup vs baseline: 1.8258x; 1.7069x over previous
#include <cuda_runtime.h>
#include <cstdint>

#define BATCH 512
#define TSEQ  64
#define P_DIM 8
#define Q_DIM 24
#define N_DIM 32
#define PQ    (P_DIM * Q_DIM)   // 192
#define CPAD  36                // padded column stride (words) for 32-row panels
#define RPAD  12                // padded row stride for row-major 32x8 panels

// Scratch (no cudaMalloc allowed)
__device__ float g_U[2 * BATCH * N_DIM * P_DIM];  // 1024 x (32x8) row-major panels

// ---------------------------------------------------------------------------
// seq_kernel: one 128-thread block per (batch, q/a) panel. 1024 blocks.
//
// Quadratic Cayley recurrence (error 2||X||^3 ~ 1e-6/step):
//   G  = X C ;  C' = C - 2G + 2XG
// X = [[0, x],[-x^T, 0]], x = 8x24. C = 32x8 panel, column-major (CPAD).
//
// Threads: tp < 64 "top" owns entry (r=tp>>3, c=tp&7), 24 FMA/phase.
//          tp >= 64 "bottom" owns rows 8+3*jg+{0,1,2}, col c; 24 FMA/phase.
// x kept in shared in BOTH layouts:
//   sx  row-major 8x24 (top reads rows as float4)
//   sxT transposed packed 24x8 (bottom reads columns as float4)
// sxT commit uses the (i=tp&7, j=tp>>3) ownership -> STS banks 8j+i cover all
// 32 banks bijectively per warp: conflict-free.
// ---------------------------------------------------------------------------
__global__ __launch_bounds__(128) void seq_kernel(
    const int*   __restrict__ s1,
    const int*   __restrict__ s2,
    const float* __restrict__ emb_q,
    const float* __restrict__ emb_a,
    const float* __restrict__ transforms)
{
    const int bid   = blockIdx.x;
    const bool is_q = (bid < BATCH);
    const int  b    = is_q ? bid : (bid - BATCH);
    const int  tp   = threadIdx.x;
    const bool top  = (tp < 64);

    const float* emb  = is_q ? emb_q : emb_a;
    const int*   sent = is_q ? s1    : s2;

    __shared__ __align__(16) float sx [2][PQ];   // row-major 8x24
    __shared__ __align__(16) float sxT[2][PQ];   // packed transposed 24x8
    __shared__ __align__(16) float sC[8 * CPAD]; // column-major padded
    __shared__ __align__(16) float sG[8 * CPAD];
    __shared__ int stok[TSEQ];

    // geometry
    const int c  = tp & 7;
    const int r  = tp >> 3;            // top only
    const int jg = (tp - 64) >> 3;     // bottom only
    const int j0 = 3 * jg;

    // x-commit ownership
    const int i1 = tp & 7;
    const int j1 = tp >> 3;            // 0..15
    const int o1 = i1 * Q_DIM + j1;    // row-major offset of sxT entry 1
    const int ta = j1 * 8 + i1;        // sxT addr 1
    const int j2 = 16 + (tp >> 3);     // top only: 16..23
    const int o2 = i1 * Q_DIM + j2;
    const int tb = j2 * 8 + i1;

    // transform factors (answer: identity)
    float tfa = 1.0f, tfb = 1.0f, tfc = 1.0f, tfd = 1.0f;
    if (is_q) {
        tfa = transforms[tp];
        tfc = transforms[o1];
        if (top) {
            tfb = transforms[tp + 128];
            tfd = transforms[o2];
        }
    }

    if (tp < TSEQ) stok[tp] = sent[b * TSEQ + tp];

    // registers: own panel entries (top uses cown0 only)
    float cown0 = 0.f, cown1 = 0.f, cown2 = 0.f;
    if (top) cown0 = (r == c) ? 1.0f : 0.0f;

    // init shared C
    if (top) {
        sC[c * CPAD + r] = cown0;
    } else {
        sC[c * CPAD + 8 + j0 + 0] = 0.0f;
        sC[c * CPAD + 8 + j0 + 1] = 0.0f;
        sC[c * CPAD + 8 + j0 + 2] = 0.0f;
    }
    __syncthreads();

    // first x (t = 63) into buffer 1, both layouts
    {
        size_t base = (size_t)stok[TSEQ - 1] * PQ;
        float va = emb[base + tp];
        float vc = emb[base + o1];
        sx [1][tp] = va * tfa;
        sxT[1][ta] = vc * tfc;
        if (top) {
            float vb = emb[base + tp + 128];
            float vd = emb[base + o2];
            sx [1][tp + 128] = vb * tfb;
            sxT[1][tb]       = vd * tfd;
        }
    }
    __syncthreads();

    float rx[24];

    for (int t = TSEQ - 1; t >= 0; --t) {
        const int buf = t & 1;

        // prefetch next token's values (L2-resident after warmup)
        float va = 0.f, vb = 0.f, vc = 0.f, vd = 0.f;
        if (t > 0) {
            size_t base = (size_t)stok[t - 1] * PQ;
            va = emb[base + tp];
            vc = emb[base + o1];
            if (top) {
                vb = emb[base + tp + 128];
                vd = emb[base + o2];
            }
        }

        // cache this step's x slice in registers
        if (top) {
            const float4* px = (const float4*)(sx[buf] + r * Q_DIM);
            #pragma unroll
            for (int m = 0; m < 6; ++m) {
                float4 v = px[m];
                rx[4*m] = v.x; rx[4*m+1] = v.y; rx[4*m+2] = v.z; rx[4*m+3] = v.w;
            }
        } else {
            #pragma unroll
            for (int d = 0; d < 3; ++d) {
                const float4* pxt = (const float4*)(sxT[buf] + (j0 + d) * 8);
                float4 v0 = pxt[0], v1 = pxt[1];
                rx[d*8+0] = v0.x; rx[d*8+1] = v0.y; rx[d*8+2] = v0.z; rx[d*8+3] = v0.w;
                rx[d*8+4] = v1.x; rx[d*8+5] = v1.y; rx[d*8+6] = v1.z; rx[d*8+7] = v1.w;
            }
        }

        // ---- Phase 1: G = X C
        float gown0, gown1 = 0.f, gown2 = 0.f;
        if (top) {
            const float4* pc = (const float4*)(&sC[c * CPAD + 8]);
            float a0 = 0.f, a1 = 0.f, a2 = 0.f, a3 = 0.f;
            #pragma unroll
            for (int m = 0; m < 6; ++m) {
                float4 v = pc[m];
                a0 += rx[4*m] * v.x;  a1 += rx[4*m+1] * v.y;
                a2 += rx[4*m+2] * v.z; a3 += rx[4*m+3] * v.w;
            }
            gown0 = (a0 + a1) + (a2 + a3);
            sG[c * CPAD + r] = gown0;
        } else {
            const float4* pc = (const float4*)(&sC[c * CPAD]);
            float4 v0 = pc[0], v1 = pc[1];
            #pragma unroll
            for (int d = 0; d < 3; ++d) {
                float g = rx[d*8+0]*v0.x + rx[d*8+1]*v0.y + rx[d*8+2]*v0.z + rx[d*8+3]*v0.w
                        + rx[d*8+4]*v1.x + rx[d*8+5]*v1.y + rx[d*8+6]*v1.z + rx[d*8+7]*v1.w;
                g = -g;
                if (d == 0) gown0 = g; else if (d == 1) gown1 = g; else gown2 = g;
                sG[c * CPAD + 8 + j0 + d] = g;
            }
        }
        __syncthreads();

        // ---- Phase 2: C' = C - 2G + 2XG (in place)
        if (top) {
            const float4* pg = (const float4*)(&sG[c * CPAD + 8]);
            float a0 = 0.f, a1 = 0.f, a2 = 0.f, a3 = 0.f;
            #pragma unroll
            for (int m = 0; m < 6; ++m) {
                float4 v = pg[m];
                a0 += rx[4*m] * v.x;  a1 += rx[4*m+1] * v.y;
                a2 += rx[4*m+2] * v.z; a3 += rx[4*m+3] * v.w;
            }
            float h = (a0 + a1) + (a2 + a3);
            cown0 += 2.0f * (h - gown0);
            sC[c * CPAD + r] = cown0;
        } else {
            const float4* pg = (const float4*)(&sG[c * CPAD]);
            float4 v0 = pg[0], v1 = pg[1];
            #pragma unroll
            for (int d = 0; d < 3; ++d) {
                float h = rx[d*8+0]*v0.x + rx[d*8+1]*v0.y + rx[d*8+2]*v0.z + rx[d*8+3]*v0.w
                        + rx[d*8+4]*v1.x + rx[d*8+5]*v1.y + rx[d*8+6]*v1.z + rx[d*8+7]*v1.w;
                h = -h;
                float go = (d == 0) ? gown0 : ((d == 1) ? gown1 : gown2);
                float cn = ((d == 0) ? cown0 : ((d == 1) ? cown1 : cown2)) + 2.0f * (h - go);
                if (d == 0) cown0 = cn; else if (d == 1) cown1 = cn; else cown2 = cn;
                sC[c * CPAD + 8 + j0 + d] = cn;
            }
        }

        // commit next x into the other buffer (both layouts)
        if (t > 0) {
            const int nb = buf ^ 1;
            sx [nb][tp] = va * tfa;
            sxT[nb][ta] = vc * tfc;
            if (top) {
                sx [nb][tp + 128] = vb * tfb;
                sxT[nb][tb]       = vd * tfd;
            }
        }
        __syncthreads();
    }

    // write final panel row-major to global
    {
        int idx = tp;
        g_U[(size_t)bid * 256 + idx] = sC[(idx & 7) * CPAD + (idx >> 3)];
        idx = tp + 128;
        g_U[(size_t)bid * 256 + idx] = sC[(idx & 7) * CPAD + (idx >> 3)];
    }
}

// ---------------------------------------------------------------------------
// dist_kernel: 512 blocks x 256. Per block: GJ-exact yb (redundant), rotate
// the question panel, Frobenius distance of the two projectors.
// ---------------------------------------------------------------------------
__global__ __launch_bounds__(256) void dist_kernel(
    const float* __restrict__ bias,
    const float* __restrict__ wf,
    const float* __restrict__ wb,
    float*       __restrict__ out)
{
    const int b   = blockIdx.x;
    const int tid = threadIdx.x;

    __shared__ __align__(16) float sQ [N_DIM * RPAD];  // question panel row-major
    __shared__ __align__(16) float sCa[N_DIM * RPAD];  // answer panel row-major
    __shared__ __align__(16) float sUq[N_DIM * RPAD];  // rotated question panel
    __shared__ __align__(16) float syb[N_DIM * CPAD];  // yb row-major padded
    __shared__ float sA8[8 * 16];
    __shared__ float sW8[PQ];
    __shared__ float sbias[PQ];
    __shared__ float red[8];

    // load panels (row-major: idx = r*8+c)
    {
        int rr = tid >> 3, cc = tid & 7;
        sQ [rr * RPAD + cc] = g_U[(size_t)b * 256 + tid];
        sCa[rr * RPAD + cc] = g_U[(size_t)(BATCH + b) * 256 + tid];
    }
    if (tid < PQ) sbias[tid] = bias[tid];
    __syncthreads();

    // A = [I + b b^T | I]
    if (tid < 128) {
        int i = tid >> 4, cc = tid & 15;
        float v;
        if (cc < 8) {
            v = (i == cc) ? 1.0f : 0.0f;
            #pragma unroll
            for (int k = 0; k < Q_DIM; ++k) v += sbias[i * Q_DIM + k] * sbias[cc * Q_DIM + k];
        } else {
            v = (i == cc - 8) ? 1.0f : 0.0f;
        }
        sA8[i * 16 + cc] = v;
    }
    __syncthreads();

    // Gauss-Jordan
    for (int k = 0; k < 8; ++k) {
        float nv = 0.0f;
        int i = tid >> 4, cc = tid & 15;
        if (tid < 128) {
            float piv = 1.0f / sA8[k * 16 + k];
            float akc = sA8[k * 16 + cc] * piv;
            nv = (i == k) ? akc : (sA8[i * 16 + cc] - sA8[i * 16 + k] * akc);
        }
        __syncthreads();
        if (tid < 128) sA8[i * 16 + cc] = nv;
        __syncthreads();
    }

    // W = K b
    if (tid < PQ) {
        int i = tid / Q_DIM, jj = tid % Q_DIM;
        float w = 0.0f;
        #pragma unroll
        for (int k = 0; k < 8; ++k) w += sA8[i * 16 + 8 + k] * sbias[k * Q_DIM + jj];
        sW8[tid] = w;
    }
    __syncthreads();

    // yb = [[2K - I, -2W], [2W^T, I - 2 b^T W]]
    #pragma unroll
    for (int e = 0; e < 4; ++e) {
        int idx = tid + 256 * e;
        int rr = idx >> 5, cc = idx & 31;
        float y;
        if (rr < 8 && cc < 8) {
            y = 2.0f * sA8[rr * 16 + 8 + cc] - ((rr == cc) ? 1.0f : 0.0f);
        } else if (rr < 8) {
            y = -2.0f * sW8[rr * Q_DIM + (cc - 8)];
        } else if (cc < 8) {
            y = 2.0f * sW8[cc * Q_DIM + (rr - 8)];
        } else {
            int jj = rr - 8, c2 = cc - 8;
            float acc = 0.0f;
            #pragma unroll
            for (int i = 0; i < 8; ++i) acc += sbias[i * Q_DIM + jj] * sW8[i * Q_DIM + c2];
            y = ((jj == c2) ? 1.0f : 0.0f) - 2.0f * acc;
        }
        syb[rr * CPAD + cc] = y;
    }
    __syncthreads();

    // Uq = yb * Q (row-major result)
    {
        int rr = tid >> 3, cc = tid & 7;
        float acc = 0.0f;
        #pragma unroll
        for (int k = 0; k < N_DIM; ++k)
            acc += syb[rr * CPAD + k] * sQ[k * RPAD + cc];
        sUq[rr * RPAD + cc] = acc;
    }
    __syncthreads();

    // dist^2 = || Uq Uq^T - Ca Ca^T ||_F^2
    float acc = 0.0f;
    #pragma unroll
    for (int e = 0; e < 4; ++e) {
        int idx = tid + 256 * e;
        int i = idx >> 5, jj = idx & 31;
        const float4* ui = (const float4*)(&sUq[i  * RPAD]);
        const float4* uj = (const float4*)(&sUq[jj * RPAD]);
        const float4* ai = (const float4*)(&sCa[i  * RPAD]);
        const float4* aj = (const float4*)(&sCa[jj * RPAD]);
        float d = 0.0f;
        #pragma unroll
        for (int m = 0; m < 2; ++m) {
            float4 a = ui[m], bq = uj[m], x = ai[m], y = aj[m];
            d += a.x * bq.x + a.y * bq.y + a.z * bq.z + a.w * bq.w;
            d -= x.x * y.x  + x.y * y.y  + x.z * y.z  + x.w * y.w;
        }
        acc += d * d;
    }

    #pragma unroll
    for (int off = 16; off > 0; off >>= 1)
        acc += __shfl_xor_sync(0xFFFFFFFFu, acc, off);
    if ((tid & 31) == 0) red[tid >> 5] = acc;
    __syncthreads();
    if (tid == 0) {
        float s = 0.0f;
        #pragma unroll
        for (int w = 0; w < 8; ++w) s += red[w];
        out[b] = -(*wf) * sqrtf(s) + (*wb);
    }
}

// ---------------------------------------------------------------------------
extern "C" void kernel_launch(void* const* d_in, const int* in_sizes, int n_in,
                              void* d_out, int out_size)
{
    const int*   s1 = (const int*)  d_in[0];   // sentence_1 [512,64]
    const int*   s2 = (const int*)  d_in[1];   // sentence_2 [512,64]
    const float* qe = (const float*)d_in[2];   // question_embedding [32000,8,24]
    const float* ae = (const float*)d_in[3];   // answer_embedding   [32000,8,24]
    const float* qt = (const float*)d_in[4];   // question_transforms [8,24]
    const float* qb = (const float*)d_in[5];   // question_bias [8,24]
    const float* wf = (const float*)d_in[6];
    const float* wb = (const float*)d_in[7];
    float* out = (float*)d_out;

    seq_kernel<<<2 * BATCH, 128>>>(s1, s2, qe, ae, qt);
    dist_kernel<<<BATCH, 256>>>(qb, wf, wb, out);
}